// round 4
// baseline (speedup 1.0000x reference)
#include <cuda_runtime.h>
#include <cstddef>

// HealEncoding: out[b, f*NLVL + l] = sum_{n<4} params[l, neigh_pix[l,n,b], f] * neigh_weight[l,n,b]
// params:       (8, 196608, 8) fp32
// neigh_pix:    (8, 4, 1000000) int32
// neigh_weight: (8, 4, 1000000) fp32
// out:          (1000000, 64) fp32

#define NLVL   8
#define FDIM   8
#define NPIX   196608
#define BATCH  1000000
#define BBLK   16                 // batch elements per tile
#define NTILES (BATCH / BBLK)     // 62500
#define GRID   912                // persistent: ~6 blocks/SM

// Levels 0-3 tables: 12+48+192+768 = 1020 pixels * 2 float4 = 2040 float4 = 32.6KB
#define TAB_F4 2040
__device__ __constant__ int c_tab_base[4] = {0, 24, 120, 504};   // float4 offsets
__device__ __constant__ int c_tab_npix[4] = {12, 48, 192, 768};

// Block (32,8): warp == one level. Pair-cooperative gather: lanes 2j,2j+1 split
// the 32B feature row of pixel j (h = lane&1 -> 16B half), 1 L1 wavefront/pixel.
// Levels 0-3 gather from SMEM (crossbar: 16B/chunk regardless of randomness)
// instead of L1-global (1 line wavefront per random pixel, 32B/128B used).
__global__ void __launch_bounds__(256, 6)
heal_encoding_kernel(const float* __restrict__ params,
                     const int*   __restrict__ neigh_pix,
                     const float* __restrict__ neigh_weight,
                     float*       __restrict__ out)
{
    __shared__ float4 s_tab[TAB_F4];       // lvl0-3 param tables, 32.6KB
    // Staging tile: 64 out-columns x 16 b, swizzle idx = c*16 + (c>>1) + j.
    // Conflict-free for both the scalar stores and the readout (verified R3).
    __shared__ float  s[64 * 16 + 32];

    const int lane = threadIdx.x;
    const int lvl  = threadIdx.y;          // warp == level
    const int j    = lane >> 1;            // batch element within tile [0,16)
    const int h    = lane & 1;             // 16B half of the 32B feature row
    const int tid  = lvl * 32 + lane;

    // One-time cooperative table load (levels 0-3), coalesced float4 copies.
    {
        const float4* __restrict__ g4 = reinterpret_cast<const float4*>(params);
        // global float4 index for level l, item i: l*(NPIX*2) + i
        for (int i = tid; i < 24;  i += 256) s_tab[0   + i] = __ldg(&g4[0 * (NPIX*2) + i]);
        for (int i = tid; i < 96;  i += 256) s_tab[24  + i] = __ldg(&g4[1 * (NPIX*2) + i]);
        for (int i = tid; i < 384; i += 256) s_tab[120 + i] = __ldg(&g4[2 * (NPIX*2) + i]);
        for (int i = tid; i < 1536;i += 256) s_tab[504 + i] = __ldg(&g4[3 * (NPIX*2) + i]);
    }
    __syncthreads();

    const bool use_lds = (lvl < 4);
    const int  tab_base = use_lds ? c_tab_base[lvl] : 0;
    const float4* __restrict__ p4 =
        reinterpret_cast<const float4*>(params) + (size_t)lvl * (NPIX * 2);

    for (int t = blockIdx.x; t < NTILES; t += GRID) {
        const int b = t * BBLK + j;

        // Coalesced idx/weight loads (pair lanes broadcast same address).
        int   pix[4];
        float w[4];
#pragma unroll
        for (int n = 0; n < 4; n++) {
            const size_t off = (size_t)(lvl * 4 + n) * BATCH + b;
            pix[n] = __ldg(&neigh_pix[off]);
            w[n]   = __ldg(&neigh_weight[off]);
        }

        float4 g[4];
        if (use_lds) {
#pragma unroll
            for (int n = 0; n < 4; n++)
                g[n] = s_tab[tab_base + pix[n] * 2 + h];
        } else {
#pragma unroll
            for (int n = 0; n < 4; n++)
                g[n] = __ldg(&p4[(size_t)pix[n] * 2 + h]);
        }

        float4 a = make_float4(0.f, 0.f, 0.f, 0.f);
#pragma unroll
        for (int n = 0; n < 4; n++) {
            a.x = fmaf(w[n], g[n].x, a.x);
            a.y = fmaf(w[n], g[n].y, a.y);
            a.z = fmaf(w[n], g[n].z, a.z);
            a.w = fmaf(w[n], g[n].w, a.w);
        }

        // Stage: this thread owns features f = 4h..4h+3; out column c = f*8+lvl.
#pragma unroll
        for (int k = 0; k < 4; k++) {
            const int c = (h * 4 + k) * NLVL + lvl;
            const float v = (k == 0) ? a.x : (k == 1) ? a.y : (k == 2) ? a.z : a.w;
            s[c * 16 + (c >> 1) + j] = v;
        }

        __syncthreads();

        // Coalesced write-out: 16 b x 64 cols = 1024 floats, 4 iters.
        float* __restrict__ outp = out + (size_t)t * BBLK * 64;
#pragma unroll
        for (int i = 0; i < 4; i++) {
            const int e  = i * 256 + tid;
            const int bl = e >> 6;
            const int c  = e & 63;
            outp[e] = s[c * 16 + (c >> 1) + bl];
        }

        __syncthreads();   // staging tile reused next iteration
    }
}

extern "C" void kernel_launch(void* const* d_in, const int* in_sizes, int n_in,
                              void* d_out, int out_size)
{
    const float* params       = (const float*)d_in[0];
    const int*   neigh_pix    = (const int*)d_in[1];
    const float* neigh_weight = (const float*)d_in[2];
    float*       out          = (float*)d_out;

    dim3 block(32, 8);
    heal_encoding_kernel<<<GRID, block>>>(params, neigh_pix, neigh_weight, out);
}